// round 3
// baseline (speedup 1.0000x reference)
#include <cuda_runtime.h>
#include <math.h>

typedef unsigned long long ull;

#define NN 50000
#define NE 1600000
#define PAD 130

#define A_SZ (144 * PAD)
#define B_SZ (128 * PAD)
#define W_SZ 18432
#define SM_FLOATS (A_SZ + B_SZ + W_SZ + 512)
#define SM_BYTES (SM_FLOATS * 4)

__device__ float g_nf1[NN * 32];
__device__ float g_nf2[NN * 32];

// ---------- packed fp32x2 helpers (sm_103a FFMA2 pipe) ----------
__device__ __forceinline__ void fma2(ull &c, ull a, ull b) {
    asm("fma.rn.f32x2 %0, %1, %2, %0;" : "+l"(c) : "l"(a), "l"(b));
}
__device__ __forceinline__ ull packf2(float lo, float hi) {
    ull r; asm("mov.b64 %0, {%1, %2};" : "=l"(r) : "f"(lo), "f"(hi)); return r;
}
__device__ __forceinline__ float2 unpackf2(ull v) {
    float2 r; asm("mov.b64 {%0, %1}, %2;" : "=f"(r.x), "=f"(r.y) : "l"(v)); return r;
}

__device__ __forceinline__ void atomicMaxF(float* a, float v) {
    if (v >= 0.f) atomicMax((int*)a, __float_as_int(v));
    else          atomicMin((unsigned int*)a, (unsigned int)__float_as_int(v));
}

// stage weights [K][N] global -> smem duplicated [K][2N]: (w0,w0,w1,w1,...)
__device__ __forceinline__ void stageWdup(float* Wd, const float* __restrict__ Wg,
                                          int n, int t) {
    const float2* s = (const float2*)Wg;
    float4* d = (float4*)Wd;
    for (int i = t; i < n / 2; i += 256) {
        float2 w = s[i];
        d[i] = make_float4(w.x, w.x, w.y, w.y);
    }
}

// C[m][n] = sum_k A[k][m]*W[k][n] + bias[n].  A/C feature-major, stride PAD.
// 256 thr = 32 m-pair lanes x 8 n-groups. Thread covers m pairs {2tm,2tm+1} and
// {64+2tm,64+2tm+1}, n in [n0, n0+NT). Wd duplicated [K][2N].
template<int K, int N, int NT, bool RELU>
__device__ __forceinline__ void gemm2(const float* A, const float* Wd,
                                      const float* __restrict__ bias, float* C, int t) {
    const int tm2 = (t & 31) * 2;
    const int n0 = (t >> 5) * NT;
    ull acc[2][NT];
#pragma unroll
    for (int j = 0; j < NT; j++) {
        float b = (n0 + j < N) ? bias[n0 + j] : 0.f;
        ull bb = packf2(b, b);
        acc[0][j] = bb; acc[1][j] = bb;
    }
#pragma unroll 8
    for (int k = 0; k < K; k++) {
        ull a0 = *(const ull*)(A + k * PAD + tm2);
        ull a1 = *(const ull*)(A + k * PAD + tm2 + 64);
        const ull* wr = (const ull*)(Wd + k * 2 * N) + n0;
        if (NT % 2 == 0) {
#pragma unroll
            for (int j = 0; j < NT; j += 2) {
                ulonglong2 w = *(const ulonglong2*)(wr + j);
                fma2(acc[0][j],     a0, w.x); fma2(acc[1][j],     a1, w.x);
                fma2(acc[0][j + 1], a0, w.y); fma2(acc[1][j + 1], a1, w.y);
            }
        } else {
#pragma unroll
            for (int j = 0; j < NT; j++) {
                if (n0 + j < N) {
                    ull w = wr[j];
                    fma2(acc[0][j], a0, w); fma2(acc[1][j], a1, w);
                }
            }
        }
    }
#pragma unroll
    for (int j = 0; j < NT; j++) {
        if (n0 + j < N) {
            float* cr = C + (n0 + j) * PAD + tm2;
#pragma unroll
            for (int p = 0; p < 2; p++) {
                float2 v = unpackf2(acc[p][j]);
                if (RELU) { v.x = fmaxf(v.x, 0.2f * v.x); v.y = fmaxf(v.y, 0.2f * v.y); }
                *(float2*)(cr + p * 64) = v;
            }
        }
    }
}

extern "C" __global__ void __launch_bounds__(256)
edge_kernel(const float* __restrict__ nf, const float* __restrict__ ef,
            const int* __restrict__ src, const int* __restrict__ dst,
            const float* __restrict__ Wm1, const float* __restrict__ bm1,
            const float* __restrict__ Wm2, const float* __restrict__ bm2,
            const float* __restrict__ Wm3, const float* __restrict__ bm3,
            const float* __restrict__ Wm4, const float* __restrict__ bm4) {
    extern __shared__ float sm[];
    float* A  = sm;
    float* B  = sm + A_SZ;
    float* Ws = sm + A_SZ + B_SZ;
    int*  sidx = (int*)(sm + A_SZ + B_SZ + W_SZ);
    float* sg  = sm + A_SZ + B_SZ + W_SZ + 256;

    const int t = threadIdx.x;
    const int wid = t >> 5, lane = t & 31;
    const int e0 = blockIdx.x * 128;

    if (t < 128) sidx[t] = src[e0 + t];
    else         sidx[t] = dst[e0 + t - 128];
    __syncthreads();

    // gather: X = [nf[src] | nf[dst] | ef] -> A feature-major [144][PAD]
    for (int m = wid; m < 128; m += 8) {
        int s = sidx[m];
        A[lane * PAD + m]        = nf[s * 64 + lane];
        A[(lane + 32) * PAD + m] = nf[s * 64 + 32 + lane];
        int d = sidx[128 + m];
        A[(64 + lane) * PAD + m] = nf[d * 64 + lane];
        A[(96 + lane) * PAD + m] = nf[d * 64 + 32 + lane];
        if (lane < 16) A[(128 + lane) * PAD + m] = ef[(e0 + m) * 16 + lane];
    }
    __syncthreads();

    stageWdup(Ws, Wm1, 144 * 64, t);  __syncthreads();
    gemm2<144, 64, 8, true>(A, Ws, bm1, B, t);  __syncthreads();
    stageWdup(Ws, Wm2, 64 * 128, t);  __syncthreads();
    gemm2<64, 128, 16, true>(B, Ws, bm2, A, t); __syncthreads();
    stageWdup(Ws, Wm3, 128 * 64, t);  __syncthreads();
    gemm2<128, 64, 8, true>(A, Ws, bm3, B, t);  __syncthreads();
    stageWdup(Ws, Wm4, 64 * 65, t);   __syncthreads();
    gemm2<64, 65, 9, false>(B, Ws, bm4, A, t);  __syncthreads();

    // gates once per edge
    if (t < 128) sg[t] = 1.f / (1.f + expf(-A[t]));
    __syncthreads();

    // scatter: rows 1..32 -> atomic sum, rows 33..64 -> atomic max
    for (int idx = t; idx < 128 * 32; idx += 256) {
        int m = idx >> 5, h = idx & 31;
        float g = sg[m];
        int d = sidx[128 + m];
        atomicAdd(&g_nf1[d * 32 + h], A[(1 + h) * PAD + m] * g);
        atomicMaxF(&g_nf2[d * 32 + h], A[(33 + h) * PAD + m] * g);
    }
}

extern "C" __global__ void __launch_bounds__(256)
node_kernel(const float* __restrict__ nf,
            const float* __restrict__ Wr1, const float* __restrict__ br1,
            const float* __restrict__ Wr2, const float* __restrict__ br2,
            const float* __restrict__ Wr3, const float* __restrict__ br3,
            const float* __restrict__ Wr4, const float* __restrict__ br4,
            float* __restrict__ out) {
    extern __shared__ float sm[];
    float* A  = sm;
    float* B  = sm + A_SZ;
    float* Ws = sm + A_SZ + B_SZ;

    const int t = threadIdx.x;
    const int wid = t >> 5, lane = t & 31;
    const int n0 = blockIdx.x * 128;
    const int cnt = min(128, NN - n0);

    for (int m = wid; m < 128; m += 8) {
        int nd = n0 + min(m, cnt - 1);   // clamp: dup rows beyond cnt (ignored at store)
        A[lane * PAD + m]        = nf[nd * 64 + lane];
        A[(lane + 32) * PAD + m] = nf[nd * 64 + 32 + lane];
        A[(64 + lane) * PAD + m] = g_nf1[nd * 32 + lane];
        float v = g_nf2[nd * 32 + lane];
        A[(96 + lane) * PAD + m] = isfinite(v) ? v : 0.f;
    }
    __syncthreads();

    stageWdup(Ws, Wr1, 128 * 64, t);  __syncthreads();
    gemm2<128, 64, 8, true>(A, Ws, br1, B, t);  __syncthreads();
    stageWdup(Ws, Wr2, 64 * 128, t);  __syncthreads();
    gemm2<64, 128, 16, true>(B, Ws, br2, A, t); __syncthreads();
    stageWdup(Ws, Wr3, 128 * 64, t);  __syncthreads();
    gemm2<128, 64, 8, true>(A, Ws, br3, B, t);  __syncthreads();
    stageWdup(Ws, Wr4, 64 * 64, t);   __syncthreads();
    gemm2<64, 64, 8, false>(B, Ws, br4, A, t);  __syncthreads();

    for (int idx = t; idx < 128 * 64; idx += 256) {
        int m = idx >> 6, n = idx & 63;
        if (m < cnt) out[(n0 + m) * 64 + n] = A[n * PAD + m];
    }
}

extern "C" __global__ void init1_kernel() {
    int i = blockIdx.x * blockDim.x + threadIdx.x;
    if (i < NN * 32) g_nf1[i] = 0.f;
}
extern "C" __global__ void init2_kernel() {
    int i = blockIdx.x * blockDim.x + threadIdx.x;
    if (i < NN * 32) g_nf2[i] = -INFINITY;
}

extern "C" void kernel_launch(void* const* d_in, const int* in_sizes, int n_in,
                              void* d_out, int out_size) {
    (void)in_sizes; (void)n_in; (void)out_size;
    const float* nf = (const float*)d_in[0];
    const float* ef = (const float*)d_in[1];
    const int* src  = (const int*)d_in[2];
    const int* dst  = (const int*)d_in[3];

    cudaFuncSetAttribute(edge_kernel, cudaFuncAttributeMaxDynamicSharedMemorySize, SM_BYTES);
    cudaFuncSetAttribute(node_kernel, cudaFuncAttributeMaxDynamicSharedMemorySize, SM_BYTES);

    init1_kernel<<<(NN * 32 + 255) / 256, 256>>>();
    init2_kernel<<<(NN * 32 + 255) / 256, 256>>>();

    edge_kernel<<<NE / 128, 256, SM_BYTES>>>(
        nf, ef, src, dst,
        (const float*)d_in[4], (const float*)d_in[5],
        (const float*)d_in[6], (const float*)d_in[7],
        (const float*)d_in[8], (const float*)d_in[9],
        (const float*)d_in[10], (const float*)d_in[11]);

    node_kernel<<<(NN + 127) / 128, 256, SM_BYTES>>>(
        nf,
        (const float*)d_in[12], (const float*)d_in[13],
        (const float*)d_in[14], (const float*)d_in[15],
        (const float*)d_in[16], (const float*)d_in[17],
        (const float*)d_in[18], (const float*)d_in[19],
        (float*)d_out);
}